// round 10
// baseline (speedup 1.0000x reference)
#include <cuda_runtime.h>
#include <cuda_bf16.h>
#include <math.h>
#include <stdint.h>

#define SEQ 2048
#define DIM 4096
#define NH 32
#define NKV 8
#define HD 128
#define KVDIM (NKV*HD)   // 1024

// ---------------- scratch (static device globals; no allocation) ----------------
__device__ float g_q[SEQ * DIM];
__device__ float g_k[SEQ * KVDIM];
__device__ float g_v[SEQ * KVDIM];
__device__ float g_attn[SEQ * DIM];
// bf16 hi/lo split operands for GEMMs
__device__ __nv_bfloat16 g_xh[SEQ * DIM],    g_xl[SEQ * DIM];
__device__ __nv_bfloat16 g_wqh[DIM * DIM],   g_wql[DIM * DIM];
__device__ __nv_bfloat16 g_wkh[KVDIM * DIM], g_wkl[KVDIM * DIM];
__device__ __nv_bfloat16 g_wvh[KVDIM * DIM], g_wvl[KVDIM * DIM];
__device__ __nv_bfloat16 g_woh[DIM * DIM],   g_wol[DIM * DIM];
__device__ __nv_bfloat16 g_ah[SEQ * DIM],    g_al[SEQ * DIM];
// bf16 hi/lo split q/k/v for flash
__device__ __nv_bfloat16 g_qh[SEQ * DIM],    g_ql[SEQ * DIM];
__device__ __nv_bfloat16 g_kh[SEQ * KVDIM],  g_kl[SEQ * KVDIM];
__device__ __nv_bfloat16 g_vh[SEQ * KVDIM],  g_vl[SEQ * KVDIM];

// ---------------- helpers -------------------------------------------------------
__device__ __forceinline__ uint32_t smem_u32(const void* p) {
    uint32_t a;
    asm("{ .reg .u64 t; cvta.to.shared.u64 t, %1; cvt.u32.u64 %0, t; }" : "=r"(a) : "l"(p));
    return a;
}
__device__ __forceinline__ void mma_bf16(float d[4], const uint32_t a[4], const uint32_t b[2]) {
    asm volatile(
        "mma.sync.aligned.m16n8k16.row.col.f32.bf16.bf16.f32 "
        "{%0,%1,%2,%3}, {%4,%5,%6,%7}, {%8,%9}, {%0,%1,%2,%3};"
        : "+f"(d[0]), "+f"(d[1]), "+f"(d[2]), "+f"(d[3])
        : "r"(a[0]), "r"(a[1]), "r"(a[2]), "r"(a[3]), "r"(b[0]), "r"(b[1]));
}
__device__ __forceinline__ void ldmx4(uint32_t r[4], uint32_t addr) {
    asm volatile("ldmatrix.sync.aligned.m8n8.x4.shared.b16 {%0,%1,%2,%3}, [%4];"
                 : "=r"(r[0]), "=r"(r[1]), "=r"(r[2]), "=r"(r[3]) : "r"(addr));
}
__device__ __forceinline__ void ldmx2(uint32_t r[2], uint32_t addr) {
    asm volatile("ldmatrix.sync.aligned.m8n8.x2.shared.b16 {%0,%1}, [%2];"
                 : "=r"(r[0]), "=r"(r[1]) : "r"(addr));
}
__device__ __forceinline__ void ldmx2t(uint32_t r[2], uint32_t addr) {
    asm volatile("ldmatrix.sync.aligned.m8n8.x2.trans.shared.b16 {%0,%1}, [%2];"
                 : "=r"(r[0]), "=r"(r[1]) : "r"(addr));
}
#define CP16(dst, src) \
    asm volatile("cp.async.cg.shared.global [%0], [%1], 16;" :: "r"(dst), "l"(src))
#define CPCOMMIT() asm volatile("cp.async.commit_group;" ::: "memory")
#define CPWAIT0()  asm volatile("cp.async.wait_group 0;" ::: "memory")
#define CPWAIT1()  asm volatile("cp.async.wait_group 1;" ::: "memory")

__device__ __forceinline__ uint32_t pack_bf2(__nv_bfloat16 a, __nv_bfloat16 b) {
    __nv_bfloat162 t(a, b);
    return *(uint32_t*)&t;
}

// ---------------- split fp32 -> bf16 hi/lo --------------------------------------
__global__ void split_kernel(const float* __restrict__ in, __nv_bfloat16* __restrict__ hi,
                             __nv_bfloat16* __restrict__ lo, int n4) {
    int i = blockIdx.x * blockDim.x + threadIdx.x;
    if (i >= n4) return;
    float4 v = ((const float4*)in)[i];
    __nv_bfloat16 h[4], l[4];
    float vv[4] = {v.x, v.y, v.z, v.w};
#pragma unroll
    for (int e = 0; e < 4; ++e) {
        h[e] = __float2bfloat16(vv[e]);
        l[e] = __float2bfloat16(vv[e] - __bfloat162float(h[e]));
    }
    *(uint2*)(hi + 4 * (size_t)i) = *(uint2*)h;
    *(uint2*)(lo + 4 * (size_t)i) = *(uint2*)l;
}

// ---------------- fused RoPE + scale + split ------------------------------------
__global__ void rope_split(const float* __restrict__ in, __nv_bfloat16* __restrict__ hi,
                           __nv_bfloat16* __restrict__ lo, int H, float scale) {
    int idx = blockIdx.x * blockDim.x + threadIdx.x;
    int total = SEQ * H * 64;
    if (idx >= total) return;
    int i = idx & 63;
    int h = (idx >> 6) % H;
    int s = idx / (64 * H);
    float freq = __expf(-(float)i * 0.2050369299f);
    float ang = (float)s * freq;
    float c, sn;
    __sincosf(ang, &sn, &c);
    size_t base = ((size_t)s * H + h) * HD + 2 * i;
    float x0 = in[base], x1 = in[base + 1];
    float y0 = (x0 * c - x1 * sn) * scale;
    float y1 = (x0 * sn + x1 * c) * scale;
    __nv_bfloat16 h0 = __float2bfloat16(y0), h1 = __float2bfloat16(y1);
    hi[base] = h0;
    hi[base + 1] = h1;
    lo[base] = __float2bfloat16(y0 - __bfloat162float(h0));
    lo[base + 1] = __float2bfloat16(y1 - __bfloat162float(h1));
}

// ---------------- bf16x3 GEMM core: block 128x256x32 ----------------------------
// 256 threads, 8 warps (2 x 4), warp tile 64x64, m16n8k16, 3-stage cp.async.
// Stage 48KB: Ahi 8K | Alo 8K | Bhi 16K | Blo 16K. 1 CTA/SM (144KB smem).
// Smem traffic/kt = 176KB over 1536 MMA-cyc = 114.7 B/cyc < 128 B/cyc crossbar.
#define STAGE_BYTES 49152
#define GSTAGES 3
#define GSMEM_BYTES (GSTAGES * STAGE_BYTES)

__device__ __forceinline__ void gemm_tile_bf16x3(
    char* smem,
    const __nv_bfloat16* __restrict__ Ahi, const __nv_bfloat16* __restrict__ Alo,
    const __nv_bfloat16* __restrict__ Bhi, const __nv_bfloat16* __restrict__ Blo,
    float* __restrict__ C, int rowStart, int colStartB, int colStartC,
    int K, int ldC) {
    const uint32_t sb = smem_u32(smem);
    const int tid = threadIdx.x;
    const int wid = tid >> 5;
    const int l = tid & 31;
    const int wm = wid & 1;
    const int wn = wid >> 1;

    // A loader: thread -> row lr (0..127), k-half lh; two 16B chunks
    const int lr = tid >> 1;
    const int lh = tid & 1;
    const __nv_bfloat16* pAhi = Ahi + (size_t)(rowStart + lr) * K + lh * 16;
    const __nv_bfloat16* pAlo = Alo + (size_t)(rowStart + lr) * K + lh * 16;
    const int ssw = (lr >> 1) & 3;
    const uint32_t so0 = lr * 64 + (((2 * lh) ^ ssw) << 4);
    const uint32_t so1 = lr * 64 + (((2 * lh + 1) ^ ssw) << 4);
    // B loader: thread -> row tid (0..255), all 4 chunks
    const __nv_bfloat16* pBhi = Bhi + (size_t)(colStartB + tid) * K;
    const __nv_bfloat16* pBlo = Blo + (size_t)(colStartB + tid) * K;
    const int bsw = (tid >> 1) & 3;
    uint32_t bo[4];
#pragma unroll
    for (int c = 0; c < 4; ++c) bo[c] = tid * 64 + (((uint32_t)(c ^ bsw)) << 4);

    // ldmatrix lane geometry
    const int miA = l >> 3;
    const int rA0 = wm * 64 + (miA & 1) * 8 + (l & 7);
    const int swA = (rA0 >> 1) & 3;
    const int kcA0 = miA >> 1;
    const int miB = (l >> 3) & 1;
    const int rB0 = wn * 64 + (l & 7);
    const int kcB0 = miB;

    float acc[4][8][4];
#pragma unroll
    for (int mt = 0; mt < 4; ++mt)
#pragma unroll
        for (int nt = 0; nt < 8; ++nt)
#pragma unroll
            for (int r = 0; r < 4; ++r) acc[mt][nt][r] = 0.f;

    const int NK = K / 32;

#define ISSUE_STAGE(kt)                                                       \
    do {                                                                      \
        const uint32_t st = sb + (uint32_t)((kt) % GSTAGES) * STAGE_BYTES;    \
        const int kk = (kt) * 32;                                             \
        CP16(st + so0, pAhi + kk);          CP16(st + so1, pAhi + kk + 8);    \
        CP16(st + 8192 + so0, pAlo + kk);   CP16(st + 8192 + so1, pAlo + kk + 8); \
        CP16(st + 16384 + bo[0], pBhi + kk);      CP16(st + 16384 + bo[1], pBhi + kk + 8); \
        CP16(st + 16384 + bo[2], pBhi + kk + 16); CP16(st + 16384 + bo[3], pBhi + kk + 24); \
        CP16(st + 32768 + bo[0], pBlo + kk);      CP16(st + 32768 + bo[1], pBlo + kk + 8); \
        CP16(st + 32768 + bo[2], pBlo + kk + 16); CP16(st + 32768 + bo[3], pBlo + kk + 24); \
        CPCOMMIT();                                                           \
    } while (0)

    ISSUE_STAGE(0);
    ISSUE_STAGE(1);

    for (int kt = 0; kt < NK; ++kt) {
        CPWAIT1();
        __syncthreads();

        const uint32_t base = sb + (uint32_t)(kt % GSTAGES) * STAGE_BYTES;
#pragma unroll
        for (int kss = 0; kss < 2; ++kss) {
            uint32_t ahi[4][4], alo[4][4];
#pragma unroll
            for (int mt = 0; mt < 4; ++mt) {
                const uint32_t ad = base + (uint32_t)(rA0 * 64) + mt * 1024 +
                                    ((uint32_t)((kcA0 + 2 * kss) ^ swA) << 4);
                ldmx4(ahi[mt], ad);
                ldmx4(alo[mt], ad + 8192);
            }
            uint32_t bhi[8][2], blo[8][2];
#pragma unroll
            for (int nt = 0; nt < 8; ++nt) {
                const int rB = rB0 + nt * 8;
                const uint32_t bd = base + 16384 + (uint32_t)(rB * 64) +
                                    ((uint32_t)((kcB0 + 2 * kss) ^ ((rB >> 1) & 3)) << 4);
                ldmx2(bhi[nt], bd);
                ldmx2(blo[nt], bd + 16384);
            }
            // term-major (per-accumulator order hh, hl, lh preserved)
#pragma unroll
            for (int mt = 0; mt < 4; ++mt)
#pragma unroll
                for (int nt = 0; nt < 8; ++nt)
                    mma_bf16(acc[mt][nt], ahi[mt], bhi[nt]);
#pragma unroll
            for (int mt = 0; mt < 4; ++mt)
#pragma unroll
                for (int nt = 0; nt < 8; ++nt)
                    mma_bf16(acc[mt][nt], ahi[mt], blo[nt]);
#pragma unroll
            for (int mt = 0; mt < 4; ++mt)
#pragma unroll
                for (int nt = 0; nt < 8; ++nt)
                    mma_bf16(acc[mt][nt], alo[mt], bhi[nt]);
        }

        if (kt + 2 < NK) ISSUE_STAGE(kt + 2);
    }
#undef ISSUE_STAGE

    const int grp = l >> 2;
    const int tg = l & 3;
#pragma unroll
    for (int mt = 0; mt < 4; ++mt) {
        const int row = rowStart + wm * 64 + mt * 16 + grp;
#pragma unroll
        for (int nt = 0; nt < 8; ++nt) {
            const int col = colStartC + wn * 64 + nt * 8 + tg * 2;
            float2 lo = {acc[mt][nt][0], acc[mt][nt][1]};
            float2 hi = {acc[mt][nt][2], acc[mt][nt][3]};
            *(float2*)&C[(size_t)row * ldC + col] = lo;
            *(float2*)&C[(size_t)(row + 8) * ldC + col] = hi;
        }
    }
}

// ---------------- merged QKV projection (one launch, 384 CTAs) -------------------
__global__ __launch_bounds__(256) void gemm_qkv(
    const __nv_bfloat16* __restrict__ Xhi, const __nv_bfloat16* __restrict__ Xlo,
    const __nv_bfloat16* __restrict__ Wqh, const __nv_bfloat16* __restrict__ Wql,
    const __nv_bfloat16* __restrict__ Wkh, const __nv_bfloat16* __restrict__ Wkl,
    const __nv_bfloat16* __restrict__ Wvh, const __nv_bfloat16* __restrict__ Wvl,
    float* __restrict__ Q, float* __restrict__ Kc, float* __restrict__ V) {
    extern __shared__ __align__(1024) char smem[];
    const int bx = blockIdx.x;          // 0..23
    const int rowStart = blockIdx.y * 128;
    const __nv_bfloat16 *Bh, *Bl;
    float* C;
    int colB, ldC;
    if (bx < 16) {
        Bh = Wqh; Bl = Wql; C = Q; colB = bx * 256; ldC = DIM;
    } else if (bx < 20) {
        Bh = Wkh; Bl = Wkl; C = Kc; colB = (bx - 16) * 256; ldC = KVDIM;
    } else {
        Bh = Wvh; Bl = Wvl; C = V; colB = (bx - 20) * 256; ldC = KVDIM;
    }
    gemm_tile_bf16x3(smem, Xhi, Xlo, Bh, Bl, C, rowStart, colB, colB, DIM, ldC);
}

// ---------------- plain GEMM wrapper (output projection) -------------------------
__global__ __launch_bounds__(256) void gemm_bf16x3(
    const __nv_bfloat16* __restrict__ Ahi, const __nv_bfloat16* __restrict__ Alo,
    const __nv_bfloat16* __restrict__ Bhi, const __nv_bfloat16* __restrict__ Blo,
    float* __restrict__ C, int M, int N, int K) {
    extern __shared__ __align__(1024) char smem[];
    gemm_tile_bf16x3(smem, Ahi, Alo, Bhi, Blo, C, blockIdx.y * 128, blockIdx.x * 256,
                     blockIdx.x * 256, K, N);
}

// ---------------- tensor-core flash attention (causal, GQA, bf16x3) -------------
#define FSMEM_BYTES (65536 + 2 * 65536)

__global__ __launch_bounds__(256, 1) void flash_tc(
    const __nv_bfloat16* __restrict__ Qh, const __nv_bfloat16* __restrict__ Ql,
    const __nv_bfloat16* __restrict__ Kh, const __nv_bfloat16* __restrict__ Kl,
    const __nv_bfloat16* __restrict__ Vh, const __nv_bfloat16* __restrict__ Vl,
    float* __restrict__ O) {
    extern __shared__ __align__(1024) char smem[];
    const uint32_t sb = smem_u32(smem);
    const int tid = threadIdx.x;
    const int w = tid >> 5;
    const int l = tid & 31;
    const int it = (int)gridDim.x - 1 - (int)blockIdx.x;  // heavy tiles first
    const int h = blockIdx.y;
    const int kvh = h >> 2;

    {
#pragma unroll
        for (int i = 0; i < 8; ++i) {
            const int idx = tid + i * 256;
            const int rr = idx >> 4;
            const int cc = idx & 15;
            const uint32_t d0 = sb + rr * 256 + (((uint32_t)(cc ^ (rr & 7))) << 4);
            const size_t g = (size_t)(it * 128 + rr) * DIM + h * HD + cc * 8;
            CP16(d0, Qh + g);
            CP16(d0 + 32768, Ql + g);
        }
    }
    auto load_kv = [&](int jt, int p) {
        const uint32_t base = sb + 65536 + (uint32_t)p * 65536;
#pragma unroll
        for (int i = 0; i < 4; ++i) {
            const int idx = tid + i * 256;
            const int rr = idx >> 4;
            const int cc = idx & 15;
            const uint32_t off = rr * 256 + (((uint32_t)(cc ^ (rr & 7))) << 4);
            const size_t g = (size_t)(jt * 64 + rr) * KVDIM + kvh * HD + cc * 8;
            CP16(base + off, Kh + g);
            CP16(base + 16384 + off, Kl + g);
            CP16(base + 32768 + off, Vh + g);
            CP16(base + 49152 + off, Vl + g);
        }
    };

    const int nblocks = 2 * it + 2;
    load_kv(0, 0);
    CPCOMMIT();

    float m0 = -1e30f, m1 = -1e30f, l0 = 0.f, l1 = 0.f;
    float ao[16][4];
#pragma unroll
    for (int nf = 0; nf < 16; ++nf)
#pragma unroll
        for (int r = 0; r < 4; ++r) ao[nf][r] = 0.f;

    const int miA = l >> 3;
    const int qrr = w * 16 + (miA & 1) * 8 + (l & 7);
    const uint32_t qrow = sb + (uint32_t)qrr * 256;
    const int qsw = qrr & 7;
    const int qc0 = miA >> 1;
    const int l16 = l & 15;

    for (int jt = 0; jt < nblocks; ++jt) {
        const int p = jt & 1;
        CPWAIT0();
        __syncthreads();
        if (jt + 1 < nblocks) {
            load_kv(jt + 1, p ^ 1);
            CPCOMMIT();
        }
        const uint32_t kb = sb + 65536 + (uint32_t)p * 65536;

        float as[8][4];
#pragma unroll
        for (int nf = 0; nf < 8; ++nf)
#pragma unroll
            for (int r = 0; r < 4; ++r) as[nf][r] = 0.f;

#pragma unroll
        for (int ks = 0; ks < 8; ++ks) {
            const uint32_t qa = qrow + ((uint32_t)((2 * ks + qc0) ^ qsw) << 4);
            uint32_t qh4[4], ql4[4];
            ldmx4(qh4, qa);
            ldmx4(ql4, qa + 32768);
#pragma unroll
            for (int nfg = 0; nfg < 2; ++nfg) {
                uint32_t kh2[4][2], kl2[4][2];
#pragma unroll
                for (int j = 0; j < 4; ++j) {
                    const int nf = nfg * 4 + j;
                    const int kk = nf * 8 + (l16 & 7);
                    const uint32_t ka = kb + (uint32_t)kk * 256 +
                                        ((uint32_t)((2 * ks + (l16 >> 3)) ^ (kk & 7)) << 4);
                    ldmx2(kh2[j], ka);
                    ldmx2(kl2[j], ka + 16384);
                }
#pragma unroll
                for (int j = 0; j < 4; ++j) mma_bf16(as[nfg * 4 + j], qh4, kh2[j]);
#pragma unroll
                for (int j = 0; j < 4; ++j) mma_bf16(as[nfg * 4 + j], qh4, kl2[j]);
#pragma unroll
                for (int j = 0; j < 4; ++j) mma_bf16(as[nfg * 4 + j], ql4, kh2[j]);
            }
        }

        const int rg0 = it * 128 + w * 16 + (l >> 2);
        if (jt >= 2 * it) {
#pragma unroll
            for (int nf = 0; nf < 8; ++nf) {
                const int c0 = jt * 64 + nf * 8 + 2 * (l & 3);
                if (c0 > rg0) as[nf][0] = -1e30f;
                if (c0 + 1 > rg0) as[nf][1] = -1e30f;
                if (c0 > rg0 + 8) as[nf][2] = -1e30f;
                if (c0 + 1 > rg0 + 8) as[nf][3] = -1e30f;
            }
        }

        float mx0 = -1e30f, mx1 = -1e30f;
#pragma unroll
        for (int nf = 0; nf < 8; ++nf) {
            mx0 = fmaxf(mx0, fmaxf(as[nf][0], as[nf][1]));
            mx1 = fmaxf(mx1, fmaxf(as[nf][2], as[nf][3]));
        }
        mx0 = fmaxf(mx0, __shfl_xor_sync(0xffffffffu, mx0, 1));
        mx0 = fmaxf(mx0, __shfl_xor_sync(0xffffffffu, mx0, 2));
        mx1 = fmaxf(mx1, __shfl_xor_sync(0xffffffffu, mx1, 1));
        mx1 = fmaxf(mx1, __shfl_xor_sync(0xffffffffu, mx1, 2));
        const float mn0 = fmaxf(m0, mx0), mn1 = fmaxf(m1, mx1);
        const float al0 = __expf(m0 - mn0), al1 = __expf(m1 - mn1);

        float rs0 = 0.f, rs1 = 0.f;
        uint32_t phi[8][2], plo[8][2];
#pragma unroll
        for (int nf = 0; nf < 8; ++nf) {
            float p0 = __expf(as[nf][0] - mn0);
            float p1 = __expf(as[nf][1] - mn0);
            float p2 = __expf(as[nf][2] - mn1);
            float p3 = __expf(as[nf][3] - mn1);
            rs0 += p0 + p1;
            rs1 += p2 + p3;
            __nv_bfloat16 h0 = __float2bfloat16(p0), h1 = __float2bfloat16(p1);
            __nv_bfloat16 h2 = __float2bfloat16(p2), h3 = __float2bfloat16(p3);
            phi[nf][0] = pack_bf2(h0, h1);
            phi[nf][1] = pack_bf2(h2, h3);
            plo[nf][0] = pack_bf2(__float2bfloat16(p0 - __bfloat162float(h0)),
                                  __float2bfloat16(p1 - __bfloat162float(h1)));
            plo[nf][1] = pack_bf2(__float2bfloat16(p2 - __bfloat162float(h2)),
                                  __float2bfloat16(p3 - __bfloat162float(h3)));
        }
        rs0 += __shfl_xor_sync(0xffffffffu, rs0, 1);
        rs0 += __shfl_xor_sync(0xffffffffu, rs0, 2);
        rs1 += __shfl_xor_sync(0xffffffffu, rs1, 1);
        rs1 += __shfl_xor_sync(0xffffffffu, rs1, 2);
        l0 = l0 * al0 + rs0;
        l1 = l1 * al1 + rs1;
        m0 = mn0;
        m1 = mn1;
#pragma unroll
        for (int nf = 0; nf < 16; ++nf) {
            ao[nf][0] *= al0;
            ao[nf][1] *= al0;
            ao[nf][2] *= al1;
            ao[nf][3] *= al1;
        }

        const uint32_t vb = kb + 32768;
#pragma unroll
        for (int ks2 = 0; ks2 < 4; ++ks2) {
            const uint32_t aph[4] = {phi[2 * ks2][0], phi[2 * ks2][1],
                                     phi[2 * ks2 + 1][0], phi[2 * ks2 + 1][1]};
            const uint32_t apl[4] = {plo[2 * ks2][0], plo[2 * ks2][1],
                                     plo[2 * ks2 + 1][0], plo[2 * ks2 + 1][1]};
            const int kk = ks2 * 16 + (l16 & 7) + 8 * (l16 >> 3);
#pragma unroll
            for (int nfg = 0; nfg < 4; ++nfg) {
                uint32_t vh2[4][2], vl2[4][2];
#pragma unroll
                for (int j = 0; j < 4; ++j) {
                    const int nf2 = nfg * 4 + j;
                    const uint32_t va = vb + (uint32_t)kk * 256 +
                                        ((uint32_t)(nf2 ^ (kk & 7)) << 4);
                    ldmx2t(vh2[j], va);
                    ldmx2t(vl2[j], va + 16384);
                }
#pragma unroll
                for (int j = 0; j < 4; ++j) mma_bf16(ao[nfg * 4 + j], aph, vh2[j]);
#pragma unroll
                for (int j = 0; j < 4; ++j) mma_bf16(ao[nfg * 4 + j], aph, vl2[j]);
#pragma unroll
                for (int j = 0; j < 4; ++j) mma_bf16(ao[nfg * 4 + j], apl, vh2[j]);
            }
        }
    }

    const float inv0 = 1.0f / l0, inv1 = 1.0f / l1;
    const int rg0 = it * 128 + w * 16 + (l >> 2);
#pragma unroll
    for (int nf2 = 0; nf2 < 16; ++nf2) {
        const int col = h * HD + nf2 * 8 + 2 * (l & 3);
        float2 o0 = {ao[nf2][0] * inv0, ao[nf2][1] * inv0};
        float2 o1 = {ao[nf2][2] * inv1, ao[nf2][3] * inv1};
        *(float2*)&O[(size_t)rg0 * DIM + col] = o0;
        *(float2*)&O[(size_t)(rg0 + 8) * DIM + col] = o1;
    }
}

// ---------------- launch --------------------------------------------------------
extern "C" void kernel_launch(void* const* d_in, const int* in_sizes, int n_in,
                              void* d_out, int out_size) {
    const float* x  = (const float*)d_in[0];
    const float* wq = (const float*)d_in[1];
    const float* wk = (const float*)d_in[2];
    const float* wv = (const float*)d_in[3];
    const float* wo = (const float*)d_in[4];
    float* out = (float*)d_out;

    float *qp, *kp, *vp, *ap;
    cudaGetSymbolAddress((void**)&qp, g_q);
    cudaGetSymbolAddress((void**)&kp, g_k);
    cudaGetSymbolAddress((void**)&vp, g_v);
    cudaGetSymbolAddress((void**)&ap, g_attn);

    __nv_bfloat16 *xh, *xl, *wqh, *wql, *wkh, *wkl, *wvh, *wvl, *woh, *wol, *ah, *al;
    __nv_bfloat16 *qh, *ql, *kh, *kl, *vh, *vl;
    cudaGetSymbolAddress((void**)&xh, g_xh);   cudaGetSymbolAddress((void**)&xl, g_xl);
    cudaGetSymbolAddress((void**)&wqh, g_wqh); cudaGetSymbolAddress((void**)&wql, g_wql);
    cudaGetSymbolAddress((void**)&wkh, g_wkh); cudaGetSymbolAddress((void**)&wkl, g_wkl);
    cudaGetSymbolAddress((void**)&wvh, g_wvh); cudaGetSymbolAddress((void**)&wvl, g_wvl);
    cudaGetSymbolAddress((void**)&woh, g_woh); cudaGetSymbolAddress((void**)&wol, g_wol);
    cudaGetSymbolAddress((void**)&ah, g_ah);   cudaGetSymbolAddress((void**)&al, g_al);
    cudaGetSymbolAddress((void**)&qh, g_qh);   cudaGetSymbolAddress((void**)&ql, g_ql);
    cudaGetSymbolAddress((void**)&kh, g_kh);   cudaGetSymbolAddress((void**)&kl, g_kl);
    cudaGetSymbolAddress((void**)&vh, g_vh);   cudaGetSymbolAddress((void**)&vl, g_vl);

    cudaFuncSetAttribute(gemm_qkv, cudaFuncAttributeMaxDynamicSharedMemorySize, GSMEM_BYTES);
    cudaFuncSetAttribute(gemm_bf16x3, cudaFuncAttributeMaxDynamicSharedMemorySize, GSMEM_BYTES);
    cudaFuncSetAttribute(flash_tc, cudaFuncAttributeMaxDynamicSharedMemorySize, FSMEM_BYTES);

    // Split inputs to bf16 hi/lo
    {
        int n4;
        n4 = SEQ * DIM / 4;    split_kernel<<<(n4 + 255) / 256, 256>>>(x, xh, xl, n4);
        n4 = DIM * DIM / 4;    split_kernel<<<(n4 + 255) / 256, 256>>>(wq, wqh, wql, n4);
        n4 = KVDIM * DIM / 4;  split_kernel<<<(n4 + 255) / 256, 256>>>(wk, wkh, wkl, n4);
        n4 = KVDIM * DIM / 4;  split_kernel<<<(n4 + 255) / 256, 256>>>(wv, wvh, wvl, n4);
        n4 = DIM * DIM / 4;    split_kernel<<<(n4 + 255) / 256, 256>>>(wo, woh, wol, n4);
    }

    // Merged Q/K/V projections (one launch, 384 CTAs of 128x256)
    gemm_qkv<<<dim3(24, SEQ / 128), 256, GSMEM_BYTES>>>(xh, xl, wqh, wql, wkh, wkl,
                                                        wvh, wvl, qp, kp, vp);

    // RoPE + scale + split q/k; split v
    {
        const float scale = 0.08838834764831845f;  // 1/sqrt(128)
        int totq = SEQ * NH * 64;
        rope_split<<<(totq + 255) / 256, 256>>>(qp, qh, ql, NH, scale);
        int totk = SEQ * NKV * 64;
        rope_split<<<(totk + 255) / 256, 256>>>(kp, kh, kl, NKV, 1.0f);
        int n4 = SEQ * KVDIM / 4;
        split_kernel<<<(n4 + 255) / 256, 256>>>(vp, vh, vl, n4);
    }

    // Flash attention (tensor core)
    flash_tc<<<dim3(SEQ / 128, NH), 256, FSMEM_BYTES>>>(qh, ql, kh, kl, vh, vl, ap);

    // Split attention output, then output projection
    {
        int n4 = SEQ * DIM / 4;
        split_kernel<<<(n4 + 255) / 256, 256>>>(ap, ah, al, n4);
    }
    gemm_bf16x3<<<dim3(DIM / 256, SEQ / 128), 256, GSMEM_BYTES>>>(ah, al, woh, wol, out, SEQ, DIM, DIM);
}

// round 11
// speedup vs baseline: 1.2272x; 1.2272x over previous
#include <cuda_runtime.h>
#include <cuda_bf16.h>
#include <math.h>
#include <stdint.h>

#define SEQ 2048
#define DIM 4096
#define NH 32
#define NKV 8
#define HD 128
#define KVDIM (NKV*HD)   // 1024

// ---------------- scratch (static device globals; no allocation) ----------------
// bf16 hi/lo split operands for GEMMs
__device__ __nv_bfloat16 g_xh[SEQ * DIM],    g_xl[SEQ * DIM];
__device__ __nv_bfloat16 g_wqh[DIM * DIM],   g_wql[DIM * DIM];
__device__ __nv_bfloat16 g_wkh[KVDIM * DIM], g_wkl[KVDIM * DIM];
__device__ __nv_bfloat16 g_wvh[KVDIM * DIM], g_wvl[KVDIM * DIM];
__device__ __nv_bfloat16 g_woh[DIM * DIM],   g_wol[DIM * DIM];
__device__ __nv_bfloat16 g_ah[SEQ * DIM],    g_al[SEQ * DIM];
// bf16 hi/lo split q/k/v for flash (written directly by gemm_qkv epilogue)
__device__ __nv_bfloat16 g_qh[SEQ * DIM],    g_ql[SEQ * DIM];
__device__ __nv_bfloat16 g_kh[SEQ * KVDIM],  g_kl[SEQ * KVDIM];
__device__ __nv_bfloat16 g_vh[SEQ * KVDIM],  g_vl[SEQ * KVDIM];

// ---------------- helpers -------------------------------------------------------
__device__ __forceinline__ uint32_t smem_u32(const void* p) {
    uint32_t a;
    asm("{ .reg .u64 t; cvta.to.shared.u64 t, %1; cvt.u32.u64 %0, t; }" : "=r"(a) : "l"(p));
    return a;
}
__device__ __forceinline__ void mma_bf16(float d[4], const uint32_t a[4], const uint32_t b[2]) {
    asm volatile(
        "mma.sync.aligned.m16n8k16.row.col.f32.bf16.bf16.f32 "
        "{%0,%1,%2,%3}, {%4,%5,%6,%7}, {%8,%9}, {%0,%1,%2,%3};"
        : "+f"(d[0]), "+f"(d[1]), "+f"(d[2]), "+f"(d[3])
        : "r"(a[0]), "r"(a[1]), "r"(a[2]), "r"(a[3]), "r"(b[0]), "r"(b[1]));
}
__device__ __forceinline__ void ldmx4(uint32_t r[4], uint32_t addr) {
    asm volatile("ldmatrix.sync.aligned.m8n8.x4.shared.b16 {%0,%1,%2,%3}, [%4];"
                 : "=r"(r[0]), "=r"(r[1]), "=r"(r[2]), "=r"(r[3]) : "r"(addr));
}
__device__ __forceinline__ void ldmx2(uint32_t r[2], uint32_t addr) {
    asm volatile("ldmatrix.sync.aligned.m8n8.x2.shared.b16 {%0,%1}, [%2];"
                 : "=r"(r[0]), "=r"(r[1]) : "r"(addr));
}
__device__ __forceinline__ void ldmx2t(uint32_t r[2], uint32_t addr) {
    asm volatile("ldmatrix.sync.aligned.m8n8.x2.trans.shared.b16 {%0,%1}, [%2];"
                 : "=r"(r[0]), "=r"(r[1]) : "r"(addr));
}
#define CP16(dst, src) \
    asm volatile("cp.async.cg.shared.global [%0], [%1], 16;" :: "r"(dst), "l"(src))
#define CPCOMMIT() asm volatile("cp.async.commit_group;" ::: "memory")
#define CPWAIT0()  asm volatile("cp.async.wait_group 0;" ::: "memory")
#define CPWAIT1()  asm volatile("cp.async.wait_group 1;" ::: "memory")

__device__ __forceinline__ uint32_t pack_bf2(__nv_bfloat16 a, __nv_bfloat16 b) {
    __nv_bfloat162 t(a, b);
    return *(uint32_t*)&t;
}
// split two fp32 into packed hi / packed lo bf16x2
__device__ __forceinline__ void split2(float v0, float v1, uint32_t& hi, uint32_t& lo) {
    __nv_bfloat16 h0 = __float2bfloat16(v0), h1 = __float2bfloat16(v1);
    hi = pack_bf2(h0, h1);
    lo = pack_bf2(__float2bfloat16(v0 - __bfloat162float(h0)),
                  __float2bfloat16(v1 - __bfloat162float(h1)));
}

// ---------------- split fp32 -> bf16 hi/lo (inputs only) ------------------------
__global__ void split_kernel(const float* __restrict__ in, __nv_bfloat16* __restrict__ hi,
                             __nv_bfloat16* __restrict__ lo, int n4) {
    int i = blockIdx.x * blockDim.x + threadIdx.x;
    if (i >= n4) return;
    float4 v = ((const float4*)in)[i];
    __nv_bfloat16 h[4], l[4];
    float vv[4] = {v.x, v.y, v.z, v.w};
#pragma unroll
    for (int e = 0; e < 4; ++e) {
        h[e] = __float2bfloat16(vv[e]);
        l[e] = __float2bfloat16(vv[e] - __bfloat162float(h[e]));
    }
    *(uint2*)(hi + 4 * (size_t)i) = *(uint2*)h;
    *(uint2*)(lo + 4 * (size_t)i) = *(uint2*)l;
}

// ---------------- bf16x3 GEMM mainloop: block 128x128x32 ------------------------
// 256 threads, 8 warps (2x4), warp tile 64x32, 3-stage cp.async, 2 CTA/SM.
#define STAGE_BYTES 32768
#define GSTAGES 3
#define GSMEM_BYTES (GSTAGES * STAGE_BYTES)

__device__ __forceinline__ void gemm_mainloop(
    char* smem,
    const __nv_bfloat16* __restrict__ Ahi, const __nv_bfloat16* __restrict__ Alo,
    const __nv_bfloat16* __restrict__ Bhi, const __nv_bfloat16* __restrict__ Blo,
    int rowStart, int colStartB, int K, float acc[4][4][4]) {
    const uint32_t sb = smem_u32(smem);
    const int tid = threadIdx.x;
    const int wid = tid >> 5;
    const int l = tid & 31;
    const int wm = wid & 1;
    const int wn = wid >> 1;

    const int lr = tid >> 1;
    const int lh = tid & 1;
    const __nv_bfloat16* pAhi = Ahi + (size_t)(rowStart + lr) * K + lh * 16;
    const __nv_bfloat16* pAlo = Alo + (size_t)(rowStart + lr) * K + lh * 16;
    const __nv_bfloat16* pBhi = Bhi + (size_t)(colStartB + lr) * K + lh * 16;
    const __nv_bfloat16* pBlo = Blo + (size_t)(colStartB + lr) * K + lh * 16;
    const int ssw = (lr >> 1) & 3;
    const uint32_t so0 = lr * 64 + (((2 * lh) ^ ssw) << 4);
    const uint32_t so1 = lr * 64 + (((2 * lh + 1) ^ ssw) << 4);

    const int miA = l >> 3;
    const int rA0 = wm * 64 + (miA & 1) * 8 + (l & 7);
    const int swA = (rA0 >> 1) & 3;
    const int kcA0 = miA >> 1;
    const int miB = (l >> 3) & 1;
    const int rB0 = wn * 32 + (l & 7);
    const int kcB0 = miB;

#pragma unroll
    for (int mt = 0; mt < 4; ++mt)
#pragma unroll
        for (int nt = 0; nt < 4; ++nt)
#pragma unroll
            for (int r = 0; r < 4; ++r) acc[mt][nt][r] = 0.f;

    const int NK = K / 32;

#define ISSUE_STAGE(kt)                                                       \
    do {                                                                      \
        const uint32_t st = sb + (uint32_t)((kt) % GSTAGES) * STAGE_BYTES;    \
        const int kk = (kt) * 32;                                             \
        CP16(st + so0, pAhi + kk);          CP16(st + so1, pAhi + kk + 8);    \
        CP16(st + 8192 + so0, pAlo + kk);   CP16(st + 8192 + so1, pAlo + kk + 8); \
        CP16(st + 16384 + so0, pBhi + kk);  CP16(st + 16384 + so1, pBhi + kk + 8); \
        CP16(st + 24576 + so0, pBlo + kk);  CP16(st + 24576 + so1, pBlo + kk + 8); \
        CPCOMMIT();                                                           \
    } while (0)

    ISSUE_STAGE(0);
    ISSUE_STAGE(1);

    for (int kt = 0; kt < NK; ++kt) {
        CPWAIT1();
        __syncthreads();

        const uint32_t base = sb + (uint32_t)(kt % GSTAGES) * STAGE_BYTES;
#pragma unroll
        for (int kss = 0; kss < 2; ++kss) {
            uint32_t ahi[4][4], alo[4][4];
#pragma unroll
            for (int mt = 0; mt < 4; ++mt) {
                const uint32_t ad = base + (uint32_t)(rA0 * 64) + mt * 1024 +
                                    ((uint32_t)((kcA0 + 2 * kss) ^ swA) << 4);
                ldmx4(ahi[mt], ad);
                ldmx4(alo[mt], ad + 8192);
            }
            uint32_t bhi[4][2], blo[4][2];
#pragma unroll
            for (int nt = 0; nt < 4; ++nt) {
                const int rB = rB0 + nt * 8;
                const uint32_t bd = base + 16384 + (uint32_t)(rB * 64) +
                                    ((uint32_t)((kcB0 + 2 * kss) ^ ((rB >> 1) & 3)) << 4);
                ldmx2(bhi[nt], bd);
                ldmx2(blo[nt], bd + 8192);
            }
#pragma unroll
            for (int mt = 0; mt < 4; ++mt)
#pragma unroll
                for (int nt = 0; nt < 4; ++nt)
                    mma_bf16(acc[mt][nt], ahi[mt], bhi[nt]);
#pragma unroll
            for (int mt = 0; mt < 4; ++mt)
#pragma unroll
                for (int nt = 0; nt < 4; ++nt)
                    mma_bf16(acc[mt][nt], ahi[mt], blo[nt]);
#pragma unroll
            for (int mt = 0; mt < 4; ++mt)
#pragma unroll
                for (int nt = 0; nt < 4; ++nt)
                    mma_bf16(acc[mt][nt], alo[mt], bhi[nt]);
        }

        if (kt + 2 < NK) ISSUE_STAGE(kt + 2);
    }
#undef ISSUE_STAGE
}

// ---------------- merged QKV projection + fused RoPE + hi/lo split ---------------
// grid (48, 16): bx 0..31 -> Q (rope+scale), 32..39 -> K (rope), 40..47 -> V (split)
__global__ __launch_bounds__(256) void gemm_qkv(
    const __nv_bfloat16* __restrict__ Xhi, const __nv_bfloat16* __restrict__ Xlo,
    const __nv_bfloat16* __restrict__ Wqh, const __nv_bfloat16* __restrict__ Wql,
    const __nv_bfloat16* __restrict__ Wkh, const __nv_bfloat16* __restrict__ Wkl,
    const __nv_bfloat16* __restrict__ Wvh, const __nv_bfloat16* __restrict__ Wvl,
    __nv_bfloat16* __restrict__ Qh, __nv_bfloat16* __restrict__ Ql,
    __nv_bfloat16* __restrict__ Kh, __nv_bfloat16* __restrict__ Kl,
    __nv_bfloat16* __restrict__ Vh, __nv_bfloat16* __restrict__ Vl) {
    extern __shared__ __align__(1024) char smem[];
    const int bx = blockIdx.x;
    const int rowStart = blockIdx.y * 128;
    const __nv_bfloat16 *Bh, *Bl;
    __nv_bfloat16 *Oh, *Ol;
    int colB, ldC, mode;   // mode: 0=Q(rope,scale) 1=K(rope) 2=V(split only)
    if (bx < 32) {
        Bh = Wqh; Bl = Wql; Oh = Qh; Ol = Ql; colB = bx * 128; ldC = DIM; mode = 0;
    } else if (bx < 40) {
        Bh = Wkh; Bl = Wkl; Oh = Kh; Ol = Kl; colB = (bx - 32) * 128; ldC = KVDIM; mode = 1;
    } else {
        Bh = Wvh; Bl = Wvl; Oh = Vh; Ol = Vl; colB = (bx - 40) * 128; ldC = KVDIM; mode = 2;
    }

    float acc[4][4][4];
    gemm_mainloop(smem, Xhi, Xlo, Bh, Bl, rowStart, colB, DIM, acc);

    const int tid = threadIdx.x;
    const int wid = tid >> 5;
    const int l = tid & 31;
    const int wm = wid & 1;
    const int wn = wid >> 1;
    const int grp = l >> 2;
    const int tg = l & 3;
    const float qscale = 0.08838834764831845f;  // 1/sqrt(128)

#pragma unroll
    for (int mt = 0; mt < 4; ++mt) {
        const int row0 = rowStart + wm * 64 + mt * 16 + grp;
#pragma unroll
        for (int nt = 0; nt < 4; ++nt) {
            const int col = colB + wn * 32 + nt * 8 + tg * 2;
#pragma unroll
            for (int half = 0; half < 2; ++half) {
                const int row = row0 + 8 * half;
                float v0 = acc[mt][nt][2 * half + 0];
                float v1 = acc[mt][nt][2 * half + 1];
                if (mode != 2) {
                    // RoPE on pair (2i, 2i+1): i = (col % 128) / 2
                    const int i = (col & 127) >> 1;
                    const float freq = __expf(-(float)i * 0.2050369299f);
                    const float ang = (float)row * freq;
                    float sn, cs;
                    __sincosf(ang, &sn, &cs);
                    float y0 = v0 * cs - v1 * sn;
                    float y1 = v0 * sn + v1 * cs;
                    if (mode == 0) { y0 *= qscale; y1 *= qscale; }
                    v0 = y0; v1 = y1;
                }
                uint32_t hi, lo;
                split2(v0, v1, hi, lo);
                const size_t o = (size_t)row * ldC + col;
                *(uint32_t*)(Oh + o) = hi;
                *(uint32_t*)(Ol + o) = lo;
            }
        }
    }
}

// ---------------- output projection (fp32 out) -----------------------------------
__global__ __launch_bounds__(256) void gemm_bf16x3(
    const __nv_bfloat16* __restrict__ Ahi, const __nv_bfloat16* __restrict__ Alo,
    const __nv_bfloat16* __restrict__ Bhi, const __nv_bfloat16* __restrict__ Blo,
    float* __restrict__ C, int M, int N, int K) {
    extern __shared__ __align__(1024) char smem[];
    const int rowStart = blockIdx.y * 128;
    const int colStart = blockIdx.x * 128;
    float acc[4][4][4];
    gemm_mainloop(smem, Ahi, Alo, Bhi, Blo, rowStart, colStart, K, acc);

    const int tid = threadIdx.x;
    const int wid = tid >> 5;
    const int l = tid & 31;
    const int wm = wid & 1;
    const int wn = wid >> 1;
    const int grp = l >> 2;
    const int tg = l & 3;
#pragma unroll
    for (int mt = 0; mt < 4; ++mt) {
        const int row = rowStart + wm * 64 + mt * 16 + grp;
#pragma unroll
        for (int nt = 0; nt < 4; ++nt) {
            const int col = colStart + wn * 32 + nt * 8 + tg * 2;
            float2 lo = {acc[mt][nt][0], acc[mt][nt][1]};
            float2 hi = {acc[mt][nt][2], acc[mt][nt][3]};
            *(float2*)&C[(size_t)row * N + col] = lo;
            *(float2*)&C[(size_t)(row + 8) * N + col] = hi;
        }
    }
}

// ---------------- tensor-core flash attention (causal, GQA, bf16x3) -------------
// Epilogue writes hi/lo bf16 split directly (feeds output projection).
#define FSMEM_BYTES (65536 + 2 * 65536)

__global__ __launch_bounds__(256, 1) void flash_tc(
    const __nv_bfloat16* __restrict__ Qh, const __nv_bfloat16* __restrict__ Ql,
    const __nv_bfloat16* __restrict__ Kh, const __nv_bfloat16* __restrict__ Kl,
    const __nv_bfloat16* __restrict__ Vh, const __nv_bfloat16* __restrict__ Vl,
    __nv_bfloat16* __restrict__ Oh, __nv_bfloat16* __restrict__ Ol) {
    extern __shared__ __align__(1024) char smem[];
    const uint32_t sb = smem_u32(smem);
    const int tid = threadIdx.x;
    const int w = tid >> 5;
    const int l = tid & 31;
    const int it = (int)gridDim.x - 1 - (int)blockIdx.x;  // heavy tiles first
    const int h = blockIdx.y;
    const int kvh = h >> 2;

    {
#pragma unroll
        for (int i = 0; i < 8; ++i) {
            const int idx = tid + i * 256;
            const int rr = idx >> 4;
            const int cc = idx & 15;
            const uint32_t d0 = sb + rr * 256 + (((uint32_t)(cc ^ (rr & 7))) << 4);
            const size_t g = (size_t)(it * 128 + rr) * DIM + h * HD + cc * 8;
            CP16(d0, Qh + g);
            CP16(d0 + 32768, Ql + g);
        }
    }
    auto load_kv = [&](int jt, int p) {
        const uint32_t base = sb + 65536 + (uint32_t)p * 65536;
#pragma unroll
        for (int i = 0; i < 4; ++i) {
            const int idx = tid + i * 256;
            const int rr = idx >> 4;
            const int cc = idx & 15;
            const uint32_t off = rr * 256 + (((uint32_t)(cc ^ (rr & 7))) << 4);
            const size_t g = (size_t)(jt * 64 + rr) * KVDIM + kvh * HD + cc * 8;
            CP16(base + off, Kh + g);
            CP16(base + 16384 + off, Kl + g);
            CP16(base + 32768 + off, Vh + g);
            CP16(base + 49152 + off, Vl + g);
        }
    };

    const int nblocks = 2 * it + 2;
    load_kv(0, 0);
    CPCOMMIT();

    float m0 = -1e30f, m1 = -1e30f, l0 = 0.f, l1 = 0.f;
    float ao[16][4];
#pragma unroll
    for (int nf = 0; nf < 16; ++nf)
#pragma unroll
        for (int r = 0; r < 4; ++r) ao[nf][r] = 0.f;

    const int miA = l >> 3;
    const int qrr = w * 16 + (miA & 1) * 8 + (l & 7);
    const uint32_t qrow = sb + (uint32_t)qrr * 256;
    const int qsw = qrr & 7;
    const int qc0 = miA >> 1;
    const int l16 = l & 15;

    for (int jt = 0; jt < nblocks; ++jt) {
        const int p = jt & 1;
        CPWAIT0();
        __syncthreads();
        if (jt + 1 < nblocks) {
            load_kv(jt + 1, p ^ 1);
            CPCOMMIT();
        }
        const uint32_t kb = sb + 65536 + (uint32_t)p * 65536;

        float as[8][4];
#pragma unroll
        for (int nf = 0; nf < 8; ++nf)
#pragma unroll
            for (int r = 0; r < 4; ++r) as[nf][r] = 0.f;

#pragma unroll
        for (int ks = 0; ks < 8; ++ks) {
            const uint32_t qa = qrow + ((uint32_t)((2 * ks + qc0) ^ qsw) << 4);
            uint32_t qh4[4], ql4[4];
            ldmx4(qh4, qa);
            ldmx4(ql4, qa + 32768);
#pragma unroll
            for (int nfg = 0; nfg < 2; ++nfg) {
                uint32_t kh2[4][2], kl2[4][2];
#pragma unroll
                for (int j = 0; j < 4; ++j) {
                    const int nf = nfg * 4 + j;
                    const int kk = nf * 8 + (l16 & 7);
                    const uint32_t ka = kb + (uint32_t)kk * 256 +
                                        ((uint32_t)((2 * ks + (l16 >> 3)) ^ (kk & 7)) << 4);
                    ldmx2(kh2[j], ka);
                    ldmx2(kl2[j], ka + 16384);
                }
#pragma unroll
                for (int j = 0; j < 4; ++j) mma_bf16(as[nfg * 4 + j], qh4, kh2[j]);
#pragma unroll
                for (int j = 0; j < 4; ++j) mma_bf16(as[nfg * 4 + j], qh4, kl2[j]);
#pragma unroll
                for (int j = 0; j < 4; ++j) mma_bf16(as[nfg * 4 + j], ql4, kh2[j]);
            }
        }

        const int rg0 = it * 128 + w * 16 + (l >> 2);
        if (jt >= 2 * it) {
#pragma unroll
            for (int nf = 0; nf < 8; ++nf) {
                const int c0 = jt * 64 + nf * 8 + 2 * (l & 3);
                if (c0 > rg0) as[nf][0] = -1e30f;
                if (c0 + 1 > rg0) as[nf][1] = -1e30f;
                if (c0 > rg0 + 8) as[nf][2] = -1e30f;
                if (c0 + 1 > rg0 + 8) as[nf][3] = -1e30f;
            }
        }

        float mx0 = -1e30f, mx1 = -1e30f;
#pragma unroll
        for (int nf = 0; nf < 8; ++nf) {
            mx0 = fmaxf(mx0, fmaxf(as[nf][0], as[nf][1]));
            mx1 = fmaxf(mx1, fmaxf(as[nf][2], as[nf][3]));
        }
        mx0 = fmaxf(mx0, __shfl_xor_sync(0xffffffffu, mx0, 1));
        mx0 = fmaxf(mx0, __shfl_xor_sync(0xffffffffu, mx0, 2));
        mx1 = fmaxf(mx1, __shfl_xor_sync(0xffffffffu, mx1, 1));
        mx1 = fmaxf(mx1, __shfl_xor_sync(0xffffffffu, mx1, 2));
        const float mn0 = fmaxf(m0, mx0), mn1 = fmaxf(m1, mx1);
        const float al0 = __expf(m0 - mn0), al1 = __expf(m1 - mn1);

        float rs0 = 0.f, rs1 = 0.f;
        uint32_t phi[8][2], plo[8][2];
#pragma unroll
        for (int nf = 0; nf < 8; ++nf) {
            float p0 = __expf(as[nf][0] - mn0);
            float p1 = __expf(as[nf][1] - mn0);
            float p2 = __expf(as[nf][2] - mn1);
            float p3 = __expf(as[nf][3] - mn1);
            rs0 += p0 + p1;
            rs1 += p2 + p3;
            split2(p0, p1, phi[nf][0], plo[nf][0]);
            split2(p2, p3, phi[nf][1], plo[nf][1]);
        }
        rs0 += __shfl_xor_sync(0xffffffffu, rs0, 1);
        rs0 += __shfl_xor_sync(0xffffffffu, rs0, 2);
        rs1 += __shfl_xor_sync(0xffffffffu, rs1, 1);
        rs1 += __shfl_xor_sync(0xffffffffu, rs1, 2);
        l0 = l0 * al0 + rs0;
        l1 = l1 * al1 + rs1;
        m0 = mn0;
        m1 = mn1;
#pragma unroll
        for (int nf = 0; nf < 16; ++nf) {
            ao[nf][0] *= al0;
            ao[nf][1] *= al0;
            ao[nf][2] *= al1;
            ao[nf][3] *= al1;
        }

        const uint32_t vb = kb + 32768;
#pragma unroll
        for (int ks2 = 0; ks2 < 4; ++ks2) {
            const uint32_t aph[4] = {phi[2 * ks2][0], phi[2 * ks2][1],
                                     phi[2 * ks2 + 1][0], phi[2 * ks2 + 1][1]};
            const uint32_t apl[4] = {plo[2 * ks2][0], plo[2 * ks2][1],
                                     plo[2 * ks2 + 1][0], plo[2 * ks2 + 1][1]};
            const int kk = ks2 * 16 + (l16 & 7) + 8 * (l16 >> 3);
#pragma unroll
            for (int nfg = 0; nfg < 4; ++nfg) {
                uint32_t vh2[4][2], vl2[4][2];
#pragma unroll
                for (int j = 0; j < 4; ++j) {
                    const int nf2 = nfg * 4 + j;
                    const uint32_t va = vb + (uint32_t)kk * 256 +
                                        ((uint32_t)(nf2 ^ (kk & 7)) << 4);
                    ldmx2t(vh2[j], va);
                    ldmx2t(vl2[j], va + 16384);
                }
#pragma unroll
                for (int j = 0; j < 4; ++j) mma_bf16(ao[nfg * 4 + j], aph, vh2[j]);
#pragma unroll
                for (int j = 0; j < 4; ++j) mma_bf16(ao[nfg * 4 + j], aph, vl2[j]);
#pragma unroll
                for (int j = 0; j < 4; ++j) mma_bf16(ao[nfg * 4 + j], apl, vh2[j]);
            }
        }
    }

    // epilogue: normalize + split to hi/lo bf16 (feeds O-projection directly)
    const float inv0 = 1.0f / l0, inv1 = 1.0f / l1;
    const int rg0 = it * 128 + w * 16 + (l >> 2);
#pragma unroll
    for (int nf2 = 0; nf2 < 16; ++nf2) {
        const int col = h * HD + nf2 * 8 + 2 * (l & 3);
        uint32_t hi0, lo0, hi1, lo1;
        split2(ao[nf2][0] * inv0, ao[nf2][1] * inv0, hi0, lo0);
        split2(ao[nf2][2] * inv1, ao[nf2][3] * inv1, hi1, lo1);
        const size_t o0 = (size_t)rg0 * DIM + col;
        const size_t o1 = (size_t)(rg0 + 8) * DIM + col;
        *(uint32_t*)(Oh + o0) = hi0;
        *(uint32_t*)(Ol + o0) = lo0;
        *(uint32_t*)(Oh + o1) = hi1;
        *(uint32_t*)(Ol + o1) = lo1;
    }
}

// ---------------- launch --------------------------------------------------------
extern "C" void kernel_launch(void* const* d_in, const int* in_sizes, int n_in,
                              void* d_out, int out_size) {
    const float* x  = (const float*)d_in[0];
    const float* wq = (const float*)d_in[1];
    const float* wk = (const float*)d_in[2];
    const float* wv = (const float*)d_in[3];
    const float* wo = (const float*)d_in[4];
    float* out = (float*)d_out;

    __nv_bfloat16 *xh, *xl, *wqh, *wql, *wkh, *wkl, *wvh, *wvl, *woh, *wol, *ah, *al;
    __nv_bfloat16 *qh, *ql, *kh, *kl, *vh, *vl;
    cudaGetSymbolAddress((void**)&xh, g_xh);   cudaGetSymbolAddress((void**)&xl, g_xl);
    cudaGetSymbolAddress((void**)&wqh, g_wqh); cudaGetSymbolAddress((void**)&wql, g_wql);
    cudaGetSymbolAddress((void**)&wkh, g_wkh); cudaGetSymbolAddress((void**)&wkl, g_wkl);
    cudaGetSymbolAddress((void**)&wvh, g_wvh); cudaGetSymbolAddress((void**)&wvl, g_wvl);
    cudaGetSymbolAddress((void**)&woh, g_woh); cudaGetSymbolAddress((void**)&wol, g_wol);
    cudaGetSymbolAddress((void**)&ah, g_ah);   cudaGetSymbolAddress((void**)&al, g_al);
    cudaGetSymbolAddress((void**)&qh, g_qh);   cudaGetSymbolAddress((void**)&ql, g_ql);
    cudaGetSymbolAddress((void**)&kh, g_kh);   cudaGetSymbolAddress((void**)&kl, g_kl);
    cudaGetSymbolAddress((void**)&vh, g_vh);   cudaGetSymbolAddress((void**)&vl, g_vl);

    cudaFuncSetAttribute(gemm_qkv, cudaFuncAttributeMaxDynamicSharedMemorySize, GSMEM_BYTES);
    cudaFuncSetAttribute(gemm_bf16x3, cudaFuncAttributeMaxDynamicSharedMemorySize, GSMEM_BYTES);
    cudaFuncSetAttribute(flash_tc, cudaFuncAttributeMaxDynamicSharedMemorySize, FSMEM_BYTES);

    // Split inputs to bf16 hi/lo
    {
        int n4;
        n4 = SEQ * DIM / 4;    split_kernel<<<(n4 + 255) / 256, 256>>>(x, xh, xl, n4);
        n4 = DIM * DIM / 4;    split_kernel<<<(n4 + 255) / 256, 256>>>(wq, wqh, wql, n4);
        n4 = KVDIM * DIM / 4;  split_kernel<<<(n4 + 255) / 256, 256>>>(wk, wkh, wkl, n4);
        n4 = KVDIM * DIM / 4;  split_kernel<<<(n4 + 255) / 256, 256>>>(wv, wvh, wvl, n4);
        n4 = DIM * DIM / 4;    split_kernel<<<(n4 + 255) / 256, 256>>>(wo, woh, wol, n4);
    }

    // Merged Q/K/V projections + fused RoPE + hi/lo split (one launch, 768 CTAs)
    gemm_qkv<<<dim3(48, SEQ / 128), 256, GSMEM_BYTES>>>(xh, xl, wqh, wql, wkh, wkl,
                                                        wvh, wvl, qh, ql, kh, kl, vh, vl);

    // Flash attention (tensor core); writes split hi/lo output directly
    flash_tc<<<dim3(SEQ / 128, NH), 256, FSMEM_BYTES>>>(qh, ql, kh, kl, vh, vl, ah, al);

    // Output projection
    gemm_bf16x3<<<dim3(DIM / 128, SEQ / 128), 256, GSMEM_BYTES>>>(ah, al, woh, wol, out, SEQ, DIM, DIM);
}